// round 17
// baseline (speedup 1.0000x reference)
#include <cuda_runtime.h>
#include <cuda_bf16.h>
#include <math.h>
#include <stdint.h>

// ---------------- problem constants ----------------
#define BATCH     2
#define SEQ       2048
#define TTOT      (BATCH*SEQ)        // 4096
#define DMODEL    1024
#define DINNER    2048
#define DHEAD     64
#define NHEADS    32
#define DSTATE    64
#define DCONV     4
#define CONVDIM   (DINNER + 2*DSTATE)            // 2176
#define DINPROJ   (2*DINNER + 2*DSTATE + NHEADS) // 4256
#define NLAYERS   4
#define EPSV      1e-5f

#define CHL       128
#define NCH       (SEQ/CHL)
#define TT        16
#define NTILES    (CHL/TT)

// ---------------- scratch ----------------
__device__ float g_zxbcdt[(size_t)TTOT * DINPROJ];
__device__ float g_xconv[(size_t)TTOT * CONVDIM];
__device__ float g_y[(size_t)TTOT * DINNER];
__device__ __nv_bfloat16 g_asp[(size_t)TTOT * 2 * DINNER];
__device__ __nv_bfloat16 g_bw_in [(size_t)NLAYERS * DINPROJ * 2 * DMODEL];
__device__ __nv_bfloat16 g_bw_out[(size_t)NLAYERS * DMODEL * 2 * DINNER];
__device__ float g_Sloc[(size_t)BATCH*NHEADS*NCH * DHEAD * DSTATE];
__device__ float g_Sin [(size_t)BATCH*NHEADS*NCH * DHEAD * DSTATE];
__device__ float g_cumdt[(size_t)TTOT * NHEADS];

__device__ __forceinline__ uint32_t s2u(const void* p) {
    return (uint32_t)__cvta_generic_to_shared(p);
}
__device__ __forceinline__ float softplusf(float v) {
    return (v > 20.f) ? v : log1pf(__expf(v));
}

// =========== bf16 mma.sync NT GEMM: logical K' = 3K over [hi|lo] storage ====
#define BM 128
#define BN 128
#define BK 64
#define NSTG 3
#define STG_A 16384
#define STG_BYTES (2*STG_A)
#define GEMM_SMEM_BYTES (NSTG * STG_BYTES)   // 98304 B

__device__ __forceinline__ void gemm_issue(
    const __nv_bfloat16* __restrict__ A, const __nv_bfloat16* __restrict__ B,
    int N, int K, int m0, int n0, int kbase,
    char* As, char* Bs, int tid)
{
    int offA = (kbase >= 2 * K) ? (kbase - 2 * K) : kbase;   // hi,lo,hi
    int offB = (kbase >= K)     ? (kbase - K)     : kbase;   // hi,hi,lo
    int K2 = 2 * K;
    #pragma unroll
    for (int it = 0; it < 4; it++) {
        int id  = tid + it * 256;
        int row = id >> 3;
        int ch  = id & 7;
        int sw  = ch ^ (row & 7);
        int dst = row * 128 + sw * 16;
        {
            uint32_t saddr = s2u(As + dst);
            const void* g = A + (size_t)(m0 + row) * K2 + offA + ch * 8;
            asm volatile("cp.async.cg.shared.global [%0], [%1], 16;"
                         :: "r"(saddr), "l"(g));
        }
        {
            uint32_t saddr = s2u(Bs + dst);
            int valid = (n0 + row) < N;
            const void* g = B + (valid ? ((size_t)(n0 + row) * K2 + offB + ch * 8) : 0);
            int sz = valid ? 16 : 0;
            asm volatile("cp.async.cg.shared.global [%0], [%1], 16, %2;"
                         :: "r"(saddr), "l"(g), "r"(sz));
        }
    }
}

__global__ __launch_bounds__(256, 2)
void gemm_bf16_nt(const __nv_bfloat16* __restrict__ A, const __nv_bfloat16* __restrict__ B,
                  float* __restrict__ C, int M, int N, int K, int addC)
{
    extern __shared__ __align__(16) char dynsmem[];

    int tid  = threadIdx.x;
    int lane = tid & 31;
    int wid  = tid >> 5;
    int m0 = blockIdx.y * BM;
    int n0 = blockIdx.x * BN;
    int wm = (wid & 1) * 64;
    int wn = (wid >> 1) * 32;

    float acc[4][4][4];
    #pragma unroll
    for (int a = 0; a < 4; a++)
        #pragma unroll
        for (int b = 0; b < 4; b++)
            #pragma unroll
            for (int c = 0; c < 4; c++) acc[a][b][c] = 0.f;

    int NT = (3 * K) / BK;

    #pragma unroll
    for (int s = 0; s < NSTG - 1; s++) {
        gemm_issue(A, B, N, K, m0, n0, s * BK,
                   dynsmem + s * STG_BYTES, dynsmem + s * STG_BYTES + STG_A, tid);
        asm volatile("cp.async.commit_group;" ::: "memory");
    }

    int sc = 0;
    int si = NSTG - 1;
    for (int kt = 0; kt < NT; kt++) {
        asm volatile("cp.async.wait_group 1;" ::: "memory");
        __syncthreads();
        if (kt + 2 < NT) {
            gemm_issue(A, B, N, K, m0, n0, (kt + 2) * BK,
                       dynsmem + si * STG_BYTES, dynsmem + si * STG_BYTES + STG_A, tid);
        }
        asm volatile("cp.async.commit_group;" ::: "memory");
        si = (si == NSTG - 1) ? 0 : si + 1;

        char* As = dynsmem + sc * STG_BYTES;
        char* Bs = As + STG_A;
        sc = (sc == NSTG - 1) ? 0 : sc + 1;

        #pragma unroll
        for (int ks = 0; ks < 4; ks++) {
            uint32_t af[4][4];
            uint32_t bf[4][2];
            #pragma unroll
            for (int mi = 0; mi < 4; mi++) {
                int row = wm + mi * 16 + (lane & 15);
                int ch  = ks * 2 + (lane >> 4);
                int sw  = ch ^ (row & 7);
                uint32_t addr = s2u(As + row * 128 + sw * 16);
                asm volatile("ldmatrix.sync.aligned.m8n8.x4.shared.b16 {%0,%1,%2,%3}, [%4];"
                             : "=r"(af[mi][0]), "=r"(af[mi][1]),
                               "=r"(af[mi][2]), "=r"(af[mi][3])
                             : "r"(addr));
            }
            #pragma unroll
            for (int nj = 0; nj < 4; nj += 2) {
                int row = wn + nj * 8 + (lane >> 4) * 8 + (lane & 7);
                int ch  = ks * 2 + ((lane >> 3) & 1);
                int sw  = ch ^ (row & 7);
                uint32_t addr = s2u(Bs + row * 128 + sw * 16);
                asm volatile("ldmatrix.sync.aligned.m8n8.x4.shared.b16 {%0,%1,%2,%3}, [%4];"
                             : "=r"(bf[nj][0]), "=r"(bf[nj][1]),
                               "=r"(bf[nj + 1][0]), "=r"(bf[nj + 1][1])
                             : "r"(addr));
            }
            #pragma unroll
            for (int mi = 0; mi < 4; mi++)
                #pragma unroll
                for (int nj = 0; nj < 4; nj++)
                    asm volatile(
                        "mma.sync.aligned.m16n8k16.row.col.f32.bf16.bf16.f32 "
                        "{%0,%1,%2,%3}, {%4,%5,%6,%7}, {%8,%9}, {%0,%1,%2,%3};"
                        : "+f"(acc[mi][nj][0]), "+f"(acc[mi][nj][1]),
                          "+f"(acc[mi][nj][2]), "+f"(acc[mi][nj][3])
                        : "r"(af[mi][0]), "r"(af[mi][1]),
                          "r"(af[mi][2]), "r"(af[mi][3]),
                          "r"(bf[nj][0]), "r"(bf[nj][1]));
        }
    }

    #pragma unroll
    for (int mi = 0; mi < 4; mi++) {
        int r0 = m0 + wm + mi * 16 + (lane >> 2);
        #pragma unroll
        for (int nj = 0; nj < 4; nj++) {
            int c0 = n0 + wn + nj * 8 + (lane & 3) * 2;
            if (c0 < N) {
                float2* p0 = (float2*)(C + (size_t)r0 * N + c0);
                float2* p1 = (float2*)(C + (size_t)(r0 + 8) * N + c0);
                float2 v0 = make_float2(acc[mi][nj][0], acc[mi][nj][1]);
                float2 v1 = make_float2(acc[mi][nj][2], acc[mi][nj][3]);
                if (addC) {
                    float2 o0 = *p0, o1 = *p1;
                    v0.x += o0.x; v0.y += o0.y;
                    v1.x += o1.x; v1.y += o1.y;
                }
                *p0 = v0;
                *p1 = v1;
            }
        }
    }
}

// ---------------- rmsnorm + [hi|lo] split, float4 ----------------
__global__ void rmsnorm_split_kernel(const float* __restrict__ x,
                                     const float* __restrict__ w,
                                     __nv_bfloat16* __restrict__ O)
{
    int t = blockIdx.x;
    int tid = threadIdx.x;
    const float4* xr4 = (const float4*)(x + (size_t)t * DMODEL);
    float4 v = xr4[tid];
    float lsum = v.x * v.x + v.y * v.y + v.z * v.z + v.w * v.w;

    __shared__ float wsum[8];
    int lane = tid & 31, wid = tid >> 5;
    #pragma unroll
    for (int off = 16; off > 0; off >>= 1)
        lsum += __shfl_xor_sync(0xffffffffu, lsum, off);
    if (lane == 0) wsum[wid] = lsum;
    __syncthreads();
    __shared__ float s_rs;
    if (tid == 0) {
        float tot = 0.f;
        for (int i = 0; i < 8; i++) tot += wsum[i];
        s_rs = rsqrtf(tot / (float)DMODEL + EPSV);
    }
    __syncthreads();
    float rs = s_rs;
    float4 wv = ((const float4*)w)[tid];
    float o[4] = {v.x * rs * wv.x, v.y * rs * wv.y, v.z * rs * wv.z, v.w * rs * wv.w};
    __nv_bfloat16 hi[4], lo[4];
    #pragma unroll
    for (int j = 0; j < 4; j++) {
        hi[j] = __float2bfloat16(o[j]);
        lo[j] = __float2bfloat16(o[j] - __bfloat162float(hi[j]));
    }
    __nv_bfloat16* orow = O + (size_t)t * (2 * DMODEL) + tid * 4;
    __nv_bfloat162* p0 = (__nv_bfloat162*)orow;
    __nv_bfloat162* p1 = (__nv_bfloat162*)(orow + DMODEL);
    p0[0] = __nv_bfloat162{hi[0], hi[1]};  p0[1] = __nv_bfloat162{hi[2], hi[3]};
    p1[0] = __nv_bfloat162{lo[0], lo[1]};  p1[1] = __nv_bfloat162{lo[2], lo[3]};
}

// ---------------- weight split: fp32 -> [hi | lo], float4 ----------
__global__ void split_w_kernel(const float* __restrict__ X, __nv_bfloat16* __restrict__ O,
                               int rows, int K)
{
    int i4 = blockIdx.x * blockDim.x + threadIdx.x;
    int kq = K >> 2;
    if (i4 >= rows * kq) return;
    int r = i4 / kq;
    int k = (i4 - r * kq) * 4;
    float4 x = ((const float4*)X)[i4];
    float xv[4] = {x.x, x.y, x.z, x.w};
    __nv_bfloat16 hi[4], lo[4];
    #pragma unroll
    for (int j = 0; j < 4; j++) {
        hi[j] = __float2bfloat16(xv[j]);
        lo[j] = __float2bfloat16(xv[j] - __bfloat162float(hi[j]));
    }
    __nv_bfloat16* orow = O + (size_t)r * (2 * K) + k;
    __nv_bfloat162* p0 = (__nv_bfloat162*)orow;
    __nv_bfloat162* p1 = (__nv_bfloat162*)(orow + K);
    p0[0] = __nv_bfloat162{hi[0], hi[1]};  p0[1] = __nv_bfloat162{hi[2], hi[3]};
    p1[0] = __nv_bfloat162{lo[0], lo[1]};  p1[1] = __nv_bfloat162{lo[2], lo[3]};
}

// ---------------- depthwise conv(4) + silu: 4 timesteps per thread ----------
__global__ void conv_silu_kernel(const float* __restrict__ zxbcdt,
                                 const float* __restrict__ cw,
                                 const float* __restrict__ cb,
                                 float* __restrict__ xconv)
{
    const int NC4 = CONVDIM / 4;
    int i = blockIdx.x * blockDim.x + threadIdx.x;
    if (i >= (TTOT / 4) * NC4) return;
    int c4 = i % NC4;
    int tp = i / NC4;
    int b  = tp / (SEQ / 4);
    int l0 = (tp % (SEQ / 4)) * 4;
    int ch = c4 * 4;

    float wk[DCONV][4];
    #pragma unroll
    for (int j = 0; j < 4; j++) {
        float4 w = *(const float4*)(cw + (ch + j) * DCONV);
        wk[0][j] = w.x; wk[1][j] = w.y; wk[2][j] = w.z; wk[3][j] = w.w;
    }
    float4 bb = *(const float4*)(cb + ch);

    float4 in[7];
    #pragma unroll
    for (int k = 0; k < 7; k++) {
        int ll = l0 - 3 + k;
        if (ll >= 0)
            in[k] = *(const float4*)(zxbcdt + (size_t)(b * SEQ + ll) * DINPROJ + DINNER + ch);
        else
            in[k] = make_float4(0.f, 0.f, 0.f, 0.f);
    }

    #pragma unroll
    for (int o = 0; o < 4; o++) {
        float a[4] = {bb.x, bb.y, bb.z, bb.w};
        #pragma unroll
        for (int k = 0; k < DCONV; k++) {
            float* vp = (float*)&in[o + k];
            #pragma unroll
            for (int j = 0; j < 4; j++)
                a[j] = fmaf(vp[j], wk[k][j], a[j]);
        }
        float4 ov;
        ov.x = a[0] / (1.f + __expf(-a[0]));
        ov.y = a[1] / (1.f + __expf(-a[1]));
        ov.z = a[2] / (1.f + __expf(-a[2]));
        ov.w = a[3] / (1.f + __expf(-a[3]));
        *(float4*)(xconv + (size_t)(b * SEQ + l0 + o) * CONVDIM + ch) = ov;
    }
}

// ------- SSD phase A: 2 heads/block, fused dt, triple-buffered -------
// grid = BATCH * (NHEADS/2) * NCH = 512 (single wave at 4 CTAs/SM).
// B/C smem shared across both heads; X pair rows contiguous (h0*64..+128).
__device__ __forceinline__ void ssd_local_issue2(
    const float* __restrict__ xconv, const float* __restrict__ zxbcdt,
    int tbase, int t0, int h0,
    float* sBC, float* sX, float* sdtraw, int tid)
{
    #pragma unroll
    for (int it = 0; it < 2; it++) {   // BC: 16 timesteps x 32 chunks of 16B
        int id = tid + it * 256;
        int w = id >> 5, ch = id & 31;
        const void* g = xconv + (size_t)(tbase + t0 + w) * CONVDIM + DINNER + ch * 4;
        asm volatile("cp.async.cg.shared.global [%0], [%1], 16;"
                     :: "r"(s2u(sBC + w * 128 + ch * 4)), "l"(g));
    }
    #pragma unroll
    for (int it = 0; it < 2; it++) {   // X pair: 16 timesteps x 32 chunks of 16B
        int id = tid + it * 256;
        int w = id >> 5, ch = id & 31;
        const void* g = xconv + (size_t)(tbase + t0 + w) * CONVDIM + h0 * DHEAD + ch * 4;
        asm volatile("cp.async.cg.shared.global [%0], [%1], 16;"
                     :: "r"(s2u(sX + w * 128 + ch * 4)), "l"(g));
    }
    if (tid < TT) {   // raw dt pair (h0, h0+1 adjacent): 8B
        const void* g = zxbcdt + (size_t)(tbase + t0 + tid) * DINPROJ
                        + (DINPROJ - NHEADS) + h0;
        asm volatile("cp.async.ca.shared.global [%0], [%1], 8;"
                     :: "r"(s2u(sdtraw + tid * 2)), "l"(g));
    }
}

__global__ __launch_bounds__(256, 4)
void ssd_local_kernel(const float* __restrict__ xconv,
                      const float* __restrict__ zxbcdt,
                      const float* __restrict__ dt_bias,
                      const float* __restrict__ A_log,
                      const float* __restrict__ Dvec,
                      float* __restrict__ y,
                      float* __restrict__ Sloc,
                      float* __restrict__ cumdt)
{
    int blk = blockIdx.x;                     // BATCH*16*NCH
    int c  = blk & (NCH - 1);
    int hp = (blk >> 4) & 15;
    int b  = blk >> 8;
    int h0 = hp * 2;
    float A0   = -__expf(A_log[h0]);
    float A1   = -__expf(A_log[h0 + 1]);
    float D0   = Dvec[h0];
    float D1   = Dvec[h0 + 1];
    float bi0  = dt_bias[h0];
    float bi1  = dt_bias[h0 + 1];
    int tid  = threadIdx.x;
    int p    = tid >> 2;
    int quad = tid & 3;
    int q4   = quad * 4;

    __shared__ float sBC[3][TT][128];
    __shared__ float sX[3][TT][128];          // [head*64 + p]
    __shared__ float sdtraw[3][TT][2];

    float s0[16], s1[16];
    #pragma unroll
    for (int j = 0; j < 16; j++) { s0[j] = 0.f; s1[j] = 0.f; }
    float cum = 0.f;                          // valid for tid 0,1 (their head)
    int tbase = b * SEQ + c * CHL;

    ssd_local_issue2(xconv, zxbcdt, tbase, 0, h0,
                     &sBC[0][0][0], &sX[0][0][0], &sdtraw[0][0][0], tid);
    asm volatile("cp.async.commit_group;" ::: "memory");

    for (int i = 0; i < NTILES; i++) {
        if (i + 1 < NTILES) {
            int nb = (i + 1) % 3;
            ssd_local_issue2(xconv, zxbcdt, tbase, (i + 1) * TT, h0,
                             &sBC[nb][0][0], &sX[nb][0][0], &sdtraw[nb][0][0], tid);
        }
        asm volatile("cp.async.commit_group;" ::: "memory");
        asm volatile("cp.async.wait_group 1;" ::: "memory");
        __syncthreads();

        int bf = i % 3;
        if (tid < 2) {
            float bias = (tid == 0) ? bi0 : bi1;
            float cc = cum;
            #pragma unroll
            for (int w = 0; w < TT; w++) {
                cc += softplusf(sdtraw[bf][w][tid] + bias);
                cumdt[(size_t)(tbase + i * TT + w) * NHEADS + h0 + tid] = cc;
            }
            cum = cc;
        }

        #pragma unroll
        for (int w = 0; w < TT; w++) {
            float dt0 = softplusf(sdtraw[bf][w][0] + bi0);
            float dt1 = softplusf(sdtraw[bf][w][1] + bi1);
            float da0 = __expf(dt0 * A0);
            float da1 = __expf(dt1 * A1);
            float xp0 = sX[bf][w][p] * dt0;
            float xp1 = sX[bf][w][64 + p] * dt1;
            float ac0 = 0.f, ac1 = 0.f;
            #pragma unroll
            for (int j4 = 0; j4 < 4; j4++) {
                float4 bv = *(const float4*)&sBC[bf][w][q4 + j4 * 16];
                float4 cv = *(const float4*)&sBC[bf][w][64 + q4 + j4 * 16];
                float* bvp = (float*)&bv;
                float* cvp = (float*)&cv;
                #pragma unroll
                for (int jj = 0; jj < 4; jj++) {
                    int idx = j4 * 4 + jj;
                    s0[idx] = fmaf(da0, s0[idx], xp0 * bvp[jj]);
                    ac0     = fmaf(cvp[jj], s0[idx], ac0);
                    s1[idx] = fmaf(da1, s1[idx], xp1 * bvp[jj]);
                    ac1     = fmaf(cvp[jj], s1[idx], ac1);
                }
            }
            ac0 += __shfl_xor_sync(0xffffffffu, ac0, 1);
            ac0 += __shfl_xor_sync(0xffffffffu, ac0, 2);
            ac1 += __shfl_xor_sync(0xffffffffu, ac1, 1);
            ac1 += __shfl_xor_sync(0xffffffffu, ac1, 2);
            if (quad == 0) {
                size_t yb = (size_t)(tbase + i * TT + w) * DINNER + h0 * DHEAD + p;
                y[yb]         = ac0 + D0 * sX[bf][w][p];
                y[yb + DHEAD] = ac1 + D1 * sX[bf][w][64 + p];
            }
        }
    }

    {
        int bhc0 = b * 512 + h0 * 16 + c;
        float* sl0 = Sloc + ((size_t)bhc0 * DHEAD + p) * DSTATE + q4;
        float* sl1 = Sloc + ((size_t)(bhc0 + 16) * DHEAD + p) * DSTATE + q4;
        #pragma unroll
        for (int j4 = 0; j4 < 4; j4++) {
            *(float4*)(sl0 + j4 * 16) = make_float4(s0[j4*4], s0[j4*4+1], s0[j4*4+2], s0[j4*4+3]);
            *(float4*)(sl1 + j4 * 16) = make_float4(s1[j4*4], s1[j4*4+1], s1[j4*4+2], s1[j4*4+3]);
        }
    }
}

// ---------------- SSD phase B (unchanged layout) ----------------
__global__ void ssd_combine_kernel(const float* __restrict__ Sloc,
                                   const float* __restrict__ cumdt,
                                   const float* __restrict__ A_log,
                                   float* __restrict__ Sin)
{
    int bh = blockIdx.x;
    int b = bh >> 5, h = bh & 31;
    float A = -__expf(A_log[h]);
    int tid = threadIdx.x;
    int p = tid >> 2, quad = tid & 3;
    int q4 = quad * 4;

    float4 s[4];
    #pragma unroll
    for (int j4 = 0; j4 < 4; j4++) s[j4] = make_float4(0.f, 0.f, 0.f, 0.f);

    for (int c = 0; c < NCH; c++) {
        size_t base = (((size_t)(b * 512 + h * 16 + c)) * DHEAD + p) * DSTATE + q4;
        float dec = __expf(A * cumdt[(size_t)(b * SEQ + c * CHL + CHL - 1) * NHEADS + h]);
        #pragma unroll
        for (int j4 = 0; j4 < 4; j4++) {
            float4 sl = *(const float4*)(Sloc + base + j4 * 16);
            *(float4*)(Sin + base + j4 * 16) = s[j4];
            s[j4].x = fmaf(dec, s[j4].x, sl.x);
            s[j4].y = fmaf(dec, s[j4].y, sl.y);
            s[j4].z = fmaf(dec, s[j4].z, sl.z);
            s[j4].w = fmaf(dec, s[j4].w, sl.w);
        }
    }
}

// ------- SSD phase C: 2 heads/block, triple-buffered correction -------
__device__ __forceinline__ void ssd_corr_issue2(
    const float* __restrict__ xconv, const float* __restrict__ cumdt,
    int tbase, int t0, int h0, float* sC, float* scum, int tid)
{
    {
        int w = tid >> 4, ch = tid & 15;
        const void* g = xconv + (size_t)(tbase + t0 + w) * CONVDIM
                        + DINNER + DSTATE + ch * 4;
        asm volatile("cp.async.cg.shared.global [%0], [%1], 16;"
                     :: "r"(s2u(sC + w * 64 + ch * 4)), "l"(g));
    }
    if (tid < TT) {
        const void* g = cumdt + (size_t)(tbase + t0 + tid) * NHEADS + h0;
        asm volatile("cp.async.ca.shared.global [%0], [%1], 8;"
                     :: "r"(s2u(scum + tid * 2)), "l"(g));
    }
}

__global__ __launch_bounds__(256, 4)
void ssd_correct_kernel(const float* __restrict__ xconv,
                        const float* __restrict__ cumdt,
                        const float* __restrict__ A_log,
                        const float* __restrict__ Sin,
                        float* __restrict__ y)
{
    int blk = blockIdx.x;
    int c  = blk & (NCH - 1);
    if (c == 0) return;
    int hp = (blk >> 4) & 15;
    int b  = blk >> 8;
    int h0 = hp * 2;
    float A0 = -__expf(A_log[h0]);
    float A1 = -__expf(A_log[h0 + 1]);
    int tid = threadIdx.x;
    int p = tid >> 2, quad = tid & 3;
    int q4 = quad * 4;

    float si0[16], si1[16];
    {
        int bhc0 = b * 512 + h0 * 16 + c;
        const float* sp0 = Sin + ((size_t)bhc0 * DHEAD + p) * DSTATE + q4;
        const float* sp1 = Sin + ((size_t)(bhc0 + 16) * DHEAD + p) * DSTATE + q4;
        #pragma unroll
        for (int j4 = 0; j4 < 4; j4++) {
            float4 v0 = *(const float4*)(sp0 + j4 * 16);
            float4 v1 = *(const float4*)(sp1 + j4 * 16);
            si0[j4*4] = v0.x; si0[j4*4+1] = v0.y; si0[j4*4+2] = v0.z; si0[j4*4+3] = v0.w;
            si1[j4*4] = v1.x; si1[j4*4+1] = v1.y; si1[j4*4+2] = v1.z; si1[j4*4+3] = v1.w;
        }
    }

    __shared__ float sC[3][TT][DSTATE];
    __shared__ float scum[3][TT][2];
    int tbase = b * SEQ + c * CHL;

    ssd_corr_issue2(xconv, cumdt, tbase, 0, h0, &sC[0][0][0], &scum[0][0][0], tid);
    asm volatile("cp.async.commit_group;" ::: "memory");

    for (int i = 0; i < NTILES; i++) {
        if (i + 1 < NTILES) {
            int nb = (i + 1) % 3;
            ssd_corr_issue2(xconv, cumdt, tbase, (i + 1) * TT, h0,
                            &sC[nb][0][0], &scum[nb][0][0], tid);
        }
        asm volatile("cp.async.commit_group;" ::: "memory");
        asm volatile("cp.async.wait_group 1;" ::: "memory");
        __syncthreads();

        int bf = i % 3;
        #pragma unroll
        for (int w = 0; w < TT; w++) {
            float ac0 = 0.f, ac1 = 0.f;
            #pragma unroll
            for (int j4 = 0; j4 < 4; j4++) {
                float4 cv = *(const float4*)&sC[bf][w][q4 + j4 * 16];
                float* cvp = (float*)&cv;
                #pragma unroll
                for (int jj = 0; jj < 4; jj++) {
                    ac0 = fmaf(cvp[jj], si0[j4 * 4 + jj], ac0);
                    ac1 = fmaf(cvp[jj], si1[j4 * 4 + jj], ac1);
                }
            }
            ac0 += __shfl_xor_sync(0xffffffffu, ac0, 1);
            ac0 += __shfl_xor_sync(0xffffffffu, ac0, 2);
            ac1 += __shfl_xor_sync(0xffffffffu, ac1, 1);
            ac1 += __shfl_xor_sync(0xffffffffu, ac1, 2);
            if (quad == 0) {
                float w0 = __expf(A0 * scum[bf][w][0]);
                float w1 = __expf(A1 * scum[bf][w][1]);
                size_t yb = (size_t)(tbase + i * TT + w) * DINNER + h0 * DHEAD + p;
                y[yb]         += w0 * ac0;
                y[yb + DHEAD] += w1 * ac1;
            }
        }
    }
}

// ---------------- gate + rmsnorm + [hi|lo] split (register-resident) --------
__global__ void gate_norm_split_kernel(const float* __restrict__ zxbcdt,
                                       const float* __restrict__ y,
                                       const float* __restrict__ gw,
                                       __nv_bfloat16* __restrict__ O)
{
    int t = blockIdx.x;
    int tid = threadIdx.x;
    __shared__ float wsum[8];
    const float4* zr = (const float4*)(zxbcdt + (size_t)t * DINPROJ);
    const float4* yr = (const float4*)(y + (size_t)t * DINNER);
    float4 vreg[2];
    float lsum = 0.f;
    #pragma unroll
    for (int it = 0; it < 2; it++) {
        int i4 = tid + it * 256;
        float4 z = zr[i4];
        float4 yv = yr[i4];
        float4 v;
        v.x = yv.x * (z.x / (1.f + __expf(-z.x)));
        v.y = yv.y * (z.y / (1.f + __expf(-z.y)));
        v.z = yv.z * (z.z / (1.f + __expf(-z.z)));
        v.w = yv.w * (z.w / (1.f + __expf(-z.w)));
        vreg[it] = v;
        lsum += v.x * v.x + v.y * v.y + v.z * v.z + v.w * v.w;
    }
    int lane = tid & 31, wid = tid >> 5;
    #pragma unroll
    for (int off = 16; off > 0; off >>= 1)
        lsum += __shfl_xor_sync(0xffffffffu, lsum, off);
    if (lane == 0) wsum[wid] = lsum;
    __syncthreads();
    __shared__ float s_rs;
    if (tid == 0) {
        float tot = 0.f;
        for (int i = 0; i < 8; i++) tot += wsum[i];
        s_rs = rsqrtf(tot / (float)DINNER + EPSV);
    }
    __syncthreads();
    float rs = s_rs;
    __nv_bfloat16* obase = O + (size_t)t * (2 * DINNER);
    #pragma unroll
    for (int it = 0; it < 2; it++) {
        int i4 = tid + it * 256;
        float4 v = vreg[it];
        float4 wv = ((const float4*)gw)[i4];
        float o[4] = {v.x * rs * wv.x, v.y * rs * wv.y, v.z * rs * wv.z, v.w * rs * wv.w};
        __nv_bfloat16 hi[4], lo[4];
        #pragma unroll
        for (int j = 0; j < 4; j++) {
            hi[j] = __float2bfloat16(o[j]);
            lo[j] = __float2bfloat16(o[j] - __bfloat162float(hi[j]));
        }
        __nv_bfloat16* orow = obase + i4 * 4;
        __nv_bfloat162* p0 = (__nv_bfloat162*)orow;
        __nv_bfloat162* p1 = (__nv_bfloat162*)(orow + DINNER);
        p0[0] = __nv_bfloat162{hi[0], hi[1]};  p0[1] = __nv_bfloat162{hi[2], hi[3]};
        p1[0] = __nv_bfloat162{lo[0], lo[1]};  p1[1] = __nv_bfloat162{lo[2], lo[3]};
    }
}

// ---------------- host orchestration ----------------
extern "C" void kernel_launch(void* const* d_in, const int* in_sizes, int n_in,
                              void* d_out, int out_size)
{
    const float* x        = (const float*)d_in[0];
    const float* in_w     = (const float*)d_in[1];
    const float* conv_w   = (const float*)d_in[2];
    const float* conv_b   = (const float*)d_in[3];
    const float* dt_bias  = (const float*)d_in[4];
    const float* A_log    = (const float*)d_in[5];
    const float* Dvec     = (const float*)d_in[6];
    const float* gnorm_w  = (const float*)d_in[7];
    const float* out_w    = (const float*)d_in[8];
    const float* rms_w    = (const float*)d_in[9];
    float* out = (float*)d_out;

    float *p_zx, *p_xc, *p_y, *p_sl, *p_si, *p_cd;
    __nv_bfloat16 *p_as, *p_bwin, *p_bwout;
    cudaGetSymbolAddress((void**)&p_zx, g_zxbcdt);
    cudaGetSymbolAddress((void**)&p_xc, g_xconv);
    cudaGetSymbolAddress((void**)&p_y,  g_y);
    cudaGetSymbolAddress((void**)&p_sl, g_Sloc);
    cudaGetSymbolAddress((void**)&p_si, g_Sin);
    cudaGetSymbolAddress((void**)&p_cd, g_cumdt);
    cudaGetSymbolAddress((void**)&p_as, g_asp);
    cudaGetSymbolAddress((void**)&p_bwin,  g_bw_in);
    cudaGetSymbolAddress((void**)&p_bwout, g_bw_out);

    cudaFuncSetAttribute(gemm_bf16_nt,
                         cudaFuncAttributeMaxDynamicSharedMemorySize, GEMM_SMEM_BYTES);

    cudaMemcpyAsync(out, x, (size_t)TTOT * DMODEL * sizeof(float),
                    cudaMemcpyDeviceToDevice);

    split_w_kernel<<<((size_t)NLAYERS * DINPROJ * DMODEL / 4 + 255) / 256, 256>>>(
        in_w, p_bwin, NLAYERS * DINPROJ, DMODEL);
    split_w_kernel<<<((size_t)NLAYERS * DMODEL * DINNER / 4 + 255) / 256, 256>>>(
        out_w, p_bwout, NLAYERS * DMODEL, DINNER);

    for (int layer = 0; layer < NLAYERS; layer++) {
        const __nv_bfloat16* lw_in_t  = p_bwin  + (size_t)layer * DINPROJ * 2 * DMODEL;
        const __nv_bfloat16* lw_out_t = p_bwout + (size_t)layer * DMODEL * 2 * DINNER;
        const float* lw_cw   = conv_w  + (size_t)layer * CONVDIM * DCONV;
        const float* lw_cb   = conv_b  + (size_t)layer * CONVDIM;
        const float* lw_dtb  = dt_bias + (size_t)layer * NHEADS;
        const float* lw_Alog = A_log   + (size_t)layer * NHEADS;
        const float* lw_D    = Dvec    + (size_t)layer * NHEADS;
        const float* lw_gn   = gnorm_w + (size_t)layer * DINNER;
        const float* lw_rms  = rms_w   + (size_t)layer * DMODEL;

        rmsnorm_split_kernel<<<TTOT, 256>>>(out, lw_rms, p_as);

        {
            dim3 grid((DINPROJ + BN - 1) / BN, TTOT / BM);
            gemm_bf16_nt<<<grid, 256, GEMM_SMEM_BYTES>>>(p_as, lw_in_t, p_zx,
                                                         TTOT, DINPROJ, DMODEL, 0);
        }

        {
            int total = (TTOT / 4) * (CONVDIM / 4);
            conv_silu_kernel<<<(total + 255) / 256, 256>>>(p_zx, lw_cw, lw_cb, p_xc);
        }

        ssd_local_kernel<<<BATCH * (NHEADS / 2) * NCH, 256>>>(p_xc, p_zx, lw_dtb,
                                                              lw_Alog, lw_D,
                                                              p_y, p_sl, p_cd);
        ssd_combine_kernel<<<BATCH * NHEADS, 256>>>(p_sl, p_cd, lw_Alog, p_si);
        ssd_correct_kernel<<<BATCH * (NHEADS / 2) * NCH, 256>>>(p_xc, p_cd, lw_Alog,
                                                                p_si, p_y);

        gate_norm_split_kernel<<<TTOT, 256>>>(p_zx, p_y, lw_gn, p_as);

        {
            dim3 grid(DMODEL / BN, TTOT / BM);
            gemm_bf16_nt<<<grid, 256, GEMM_SMEM_BYTES>>>(p_as, lw_out_t, out,
                                                         TTOT, DMODEL, DINNER, 1);
        }
    }
}